// round 1
// baseline (speedup 1.0000x reference)
#include <cuda_runtime.h>
#include <math.h>

#define BB 8
#define NN 4096
#define DD 1024
#define HH 1792

// Scratch (allocation-free contract): zero-init at load, re-zeroed per launch.
__device__ float g_xbar[BB * DD];   // mean_n x[b,n,:]  (atomic-accumulated)
__device__ float g_kbar[BB * HH];   // Wk @ xbar + bk
__device__ float g_u[BB * DD];      // Wq^T @ kbar      (atomic-accumulated)
__device__ float g_c[BB];           // bq . kbar        (atomic-accumulated)

// ---------------------------------------------------------------------------
// K0: zero the accumulated scratch (xbar, u, c). kbar is fully overwritten.
__global__ void k_zero() {
    int i = blockIdx.x * blockDim.x + threadIdx.x;
    if (i < BB * DD) { g_xbar[i] = 0.f; g_u[i] = 0.f; }
    if (i < BB) g_c[i] = 0.f;
}

// ---------------------------------------------------------------------------
// K1: xbar[b,d] = (1/N) sum_n x[b,n,d]
// grid (NCHUNK, B), block 256. Thread t owns float4 #t of the 1024-wide row.
// Coalesced 512B per warp per iteration; partial sums atomically merged.
#define NCHUNK 64
__global__ void k_xbar(const float* __restrict__ x) {
    const int b = blockIdx.y;
    const int nper = NN / NCHUNK;                 // 64
    const int nbase = blockIdx.x * nper;
    const int t = threadIdx.x;                    // 0..255 -> float4 index
    const float4* xp = (const float4*)(x + (size_t)b * NN * DD);

    float4 acc = make_float4(0.f, 0.f, 0.f, 0.f);
    #pragma unroll 4
    for (int n = nbase; n < nbase + nper; n++) {
        float4 v = xp[(size_t)n * (DD / 4) + t];
        acc.x += v.x; acc.y += v.y; acc.z += v.z; acc.w += v.w;
    }
    const float invN = 1.0f / (float)NN;
    float* dst = g_xbar + b * DD + t * 4;
    atomicAdd(dst + 0, acc.x * invN);
    atomicAdd(dst + 1, acc.y * invN);
    atomicAdd(dst + 2, acc.z * invN);
    atomicAdd(dst + 3, acc.w * invN);
}

// ---------------------------------------------------------------------------
// K2: kbar[b,h] = Wk[h,:] . xbar[b,:] + bk[h];  also c[b] += bq[h]*kbar[b,h]
// grid HH blocks, block 256. Wk row read once, reused for all 8 batches.
__global__ void k_kbar(const float* __restrict__ Wk,
                       const float* __restrict__ bk,
                       const float* __restrict__ bq) {
    const int h = blockIdx.x;
    const int t = threadIdx.x;
    const float4 w = ((const float4*)(Wk + (size_t)h * DD))[t];

    float acc[BB];
    #pragma unroll
    for (int b = 0; b < BB; b++) {
        float4 xb = ((const float4*)(g_xbar + b * DD))[t];
        acc[b] = w.x * xb.x + w.y * xb.y + w.z * xb.z + w.w * xb.w;
    }
    #pragma unroll
    for (int b = 0; b < BB; b++)
        #pragma unroll
        for (int o = 16; o > 0; o >>= 1)
            acc[b] += __shfl_down_sync(0xffffffffu, acc[b], o);

    __shared__ float s[8][BB];
    const int warp = t >> 5, lane = t & 31;
    if (lane == 0) {
        #pragma unroll
        for (int b = 0; b < BB; b++) s[warp][b] = acc[b];
    }
    __syncthreads();
    if (t < BB) {
        float sum = 0.f;
        #pragma unroll
        for (int w2 = 0; w2 < 8; w2++) sum += s[w2][t];
        const float kb = sum + bk[h];
        g_kbar[t * HH + h] = kb;
        atomicAdd(&g_c[t], bq[h] * kb);
    }
}

// ---------------------------------------------------------------------------
// K3: u[b,d] = sum_h Wq[h,d] * kbar[b,h]
// grid (4 d-chunks, 14 h-chunks), block 256. Thread owns one d (coalesced).
#define HCHUNK 14
__global__ void k_u(const float* __restrict__ Wq) {
    const int d = blockIdx.x * 256 + threadIdx.x;
    const int hper = HH / HCHUNK;                  // 128
    const int hbase = blockIdx.y * hper;

    float acc[BB];
    #pragma unroll
    for (int b = 0; b < BB; b++) acc[b] = 0.f;

    for (int h = hbase; h < hbase + hper; h++) {
        const float w = __ldg(&Wq[(size_t)h * DD + d]);
        #pragma unroll
        for (int b = 0; b < BB; b++)
            acc[b] += w * g_kbar[b * HH + h];      // broadcast, L2-hot
    }
    #pragma unroll
    for (int b = 0; b < BB; b++)
        atomicAdd(&g_u[b * DD + d], acc[b]);
}

// ---------------------------------------------------------------------------
// K4: scores[r] = scale * (x[r,:] . u[b,:] + c[b]),  r = b*N + n
// grid 4096 blocks x 256 threads = one warp per row. u (4 KB/batch) stays hot.
__global__ void k_scores(const float* __restrict__ x, float* __restrict__ out) {
    const int warp = threadIdx.x >> 5, lane = threadIdx.x & 31;
    const int r = blockIdx.x * 8 + warp;          // 0 .. B*N-1
    const int b = r >> 12;                        // N = 4096
    const float4* xp = (const float4*)(x + (size_t)r * DD);
    const float4* up = (const float4*)(g_u + b * DD);

    float acc = 0.f;
    #pragma unroll
    for (int i = 0; i < 8; i++) {
        float4 xv = xp[i * 32 + lane];
        float4 uv = up[i * 32 + lane];
        acc += xv.x * uv.x + xv.y * uv.y + xv.z * uv.z + xv.w * uv.w;
    }
    #pragma unroll
    for (int o = 16; o > 0; o >>= 1)
        acc += __shfl_down_sync(0xffffffffu, acc, o);

    if (lane == 0) {
        const float scale = rsqrtf((float)HH);
        out[r] = scale * (acc + g_c[b]);
    }
}

// ---------------------------------------------------------------------------
extern "C" void kernel_launch(void* const* d_in, const int* in_sizes, int n_in,
                              void* d_out, int out_size) {
    const float* x  = (const float*)d_in[0];   // [B, N, D] f32
    const float* Wq = (const float*)d_in[1];   // [H, D]    f32
    const float* bq = (const float*)d_in[2];   // [H]       f32
    const float* Wk = (const float*)d_in[3];   // [H, D]    f32
    const float* bk = (const float*)d_in[4];   // [H]       f32
    float* out = (float*)d_out;                // [B, N]    f32

    k_zero<<<(BB * DD + 255) / 256, 256>>>();
    k_xbar<<<dim3(NCHUNK, BB), 256>>>(x);
    k_kbar<<<HH, 256>>>(Wk, bk, bq);
    k_u<<<dim3(DD / 256, HCHUNK), 256>>>(Wq);
    k_scores<<<(BB * NN) / 8, 256>>>(x, out);
}

// round 2
// speedup vs baseline: 1.6557x; 1.6557x over previous
#include <cuda_runtime.h>
#include <math.h>

#define BB 8
#define NN 4096
#define DD 1024
#define HH 1792

#define NCHU 112          // h-chunks for u partials
#define HPERU 16          // 1792 / 112

// Scratch (allocation-free contract): __device__ globals.
__device__ float g_xbar[BB * DD];          // mean_n x[b,n,:]  (atomic-accumulated)
__device__ float g_kbar[BB * HH];          // Wk @ xbar + bk
__device__ float g_upart[NCHU][BB * DD];   // partial Wq^T @ kbar per h-chunk
__device__ float g_u[BB * DD];             // reduced u
__device__ float g_c[BB];                  // bq . kbar  (atomic-accumulated)

// ---------------------------------------------------------------------------
// K0: zero the atomic-accumulated scratch (xbar, c).
__global__ void k_zero() {
    int i = blockIdx.x * blockDim.x + threadIdx.x;
    if (i < BB * DD) g_xbar[i] = 0.f;
    if (i < BB) g_c[i] = 0.f;
}

// ---------------------------------------------------------------------------
// K1: xbar[b,d] = (1/N) sum_n x[b,n,d]
// grid (NCHUNK, B), block 256. Thread t owns float4 #t of the 1024-wide row.
#define NCHUNK 64
__global__ void k_xbar(const float* __restrict__ x) {
    const int b = blockIdx.y;
    const int nper = NN / NCHUNK;                 // 64
    const int nbase = blockIdx.x * nper;
    const int t = threadIdx.x;                    // 0..255 -> float4 index
    const float4* xp = (const float4*)(x + (size_t)b * NN * DD);

    float4 acc = make_float4(0.f, 0.f, 0.f, 0.f);
    #pragma unroll 4
    for (int n = nbase; n < nbase + nper; n++) {
        float4 v = xp[(size_t)n * (DD / 4) + t];
        acc.x += v.x; acc.y += v.y; acc.z += v.z; acc.w += v.w;
    }
    const float invN = 1.0f / (float)NN;
    float* dst = g_xbar + b * DD + t * 4;
    atomicAdd(dst + 0, acc.x * invN);
    atomicAdd(dst + 1, acc.y * invN);
    atomicAdd(dst + 2, acc.z * invN);
    atomicAdd(dst + 3, acc.w * invN);
}

// ---------------------------------------------------------------------------
// K2: kbar[b,h] = Wk[h,:] . xbar[b,:] + bk[h];  also c[b] += bq[h]*kbar[b,h]
// grid HH blocks, block 256. Wk row read once, reused for all 8 batches.
__global__ void k_kbar(const float* __restrict__ Wk,
                       const float* __restrict__ bk,
                       const float* __restrict__ bq) {
    const int h = blockIdx.x;
    const int t = threadIdx.x;
    const float4 w = ((const float4*)(Wk + (size_t)h * DD))[t];

    float acc[BB];
    #pragma unroll
    for (int b = 0; b < BB; b++) {
        float4 xb = ((const float4*)(g_xbar + b * DD))[t];
        acc[b] = w.x * xb.x + w.y * xb.y + w.z * xb.z + w.w * xb.w;
    }
    #pragma unroll
    for (int b = 0; b < BB; b++)
        #pragma unroll
        for (int o = 16; o > 0; o >>= 1)
            acc[b] += __shfl_down_sync(0xffffffffu, acc[b], o);

    __shared__ float s[8][BB];
    const int warp = t >> 5, lane = t & 31;
    if (lane == 0) {
        #pragma unroll
        for (int b = 0; b < BB; b++) s[warp][b] = acc[b];
    }
    __syncthreads();
    if (t < BB) {
        float sum = 0.f;
        #pragma unroll
        for (int w2 = 0; w2 < 8; w2++) sum += s[w2][t];
        const float kb = sum + bk[h];
        g_kbar[t * HH + h] = kb;
        atomicAdd(&g_c[t], bq[h] * kb);
    }
}

// ---------------------------------------------------------------------------
// K3a: u partials. Block c handles h in [c*16, c*16+16).
// 256 threads own one float4 of d each (fully coalesced Wq rows).
// kbar chunk staged in smem; broadcast LDS reads are conflict-free.
__global__ void __launch_bounds__(256) k_upart(const float* __restrict__ Wq) {
    const int c = blockIdx.x;
    const int t = threadIdx.x;
    const int hbase = c * HPERU;

    __shared__ float s_kb[HPERU][BB];
    if (t < HPERU * BB) {
        int hh = t >> 3, b = t & 7;
        s_kb[hh][b] = g_kbar[b * HH + hbase + hh];
    }
    __syncthreads();

    float4 acc[BB];
    #pragma unroll
    for (int b = 0; b < BB; b++) acc[b] = make_float4(0.f, 0.f, 0.f, 0.f);

    #pragma unroll
    for (int hh = 0; hh < HPERU; hh++) {
        const float4 w = ((const float4*)(Wq + (size_t)(hbase + hh) * DD))[t];
        #pragma unroll
        for (int b = 0; b < BB; b++) {
            const float kb = s_kb[hh][b];
            acc[b].x = fmaf(w.x, kb, acc[b].x);
            acc[b].y = fmaf(w.y, kb, acc[b].y);
            acc[b].z = fmaf(w.z, kb, acc[b].z);
            acc[b].w = fmaf(w.w, kb, acc[b].w);
        }
    }
    float4* dst = (float4*)(g_upart[c]);
    #pragma unroll
    for (int b = 0; b < BB; b++) dst[b * (DD / 4) + t] = acc[b];
}

// ---------------------------------------------------------------------------
// K3b: u[i] = sum_c upart[c][i]   (3.6 MB, L2-hot)
__global__ void k_ured() {
    const int i = blockIdx.x * 256 + threadIdx.x;   // 0 .. BB*DD-1
    float s = 0.f;
    #pragma unroll 8
    for (int c = 0; c < NCHU; c++) s += g_upart[c][i];
    g_u[i] = s;
}

// ---------------------------------------------------------------------------
// K4: scores[r] = scale * (x[r,:] . u[b,:] + c[b]),  r = b*N + n
// One warp per row; 8 independent float4 loads per lane (MLP=8).
__global__ void k_scores(const float* __restrict__ x, float* __restrict__ out) {
    const int warp = threadIdx.x >> 5, lane = threadIdx.x & 31;
    const int r = blockIdx.x * 8 + warp;          // 0 .. B*N-1
    const int b = r >> 12;                        // N = 4096
    const float4* xp = (const float4*)(x + (size_t)r * DD);
    const float4* up = (const float4*)(g_u + b * DD);

    float acc = 0.f;
    #pragma unroll
    for (int i = 0; i < 8; i++) {
        float4 xv = xp[i * 32 + lane];
        float4 uv = up[i * 32 + lane];
        acc += xv.x * uv.x + xv.y * uv.y + xv.z * uv.z + xv.w * uv.w;
    }
    #pragma unroll
    for (int o = 16; o > 0; o >>= 1)
        acc += __shfl_down_sync(0xffffffffu, acc, o);

    if (lane == 0) {
        const float scale = rsqrtf((float)HH);
        out[r] = scale * (acc + g_c[b]);
    }
}

// ---------------------------------------------------------------------------
extern "C" void kernel_launch(void* const* d_in, const int* in_sizes, int n_in,
                              void* d_out, int out_size) {
    const float* x  = (const float*)d_in[0];   // [B, N, D] f32
    const float* Wq = (const float*)d_in[1];   // [H, D]    f32
    const float* bq = (const float*)d_in[2];   // [H]       f32
    const float* Wk = (const float*)d_in[3];   // [H, D]    f32
    const float* bk = (const float*)d_in[4];   // [H]       f32
    float* out = (float*)d_out;                // [B, N]    f32

    k_zero<<<(BB * DD + 255) / 256, 256>>>();
    k_xbar<<<dim3(NCHUNK, BB), 256>>>(x);
    k_kbar<<<HH, 256>>>(Wk, bk, bq);
    k_upart<<<NCHU, 256>>>(Wq);
    k_ured<<<(BB * DD) / 256, 256>>>();
    k_scores<<<(BB * NN) / 8, 256>>>(x, out);
}